// round 3
// baseline (speedup 1.0000x reference)
#include <cuda_runtime.h>

// KVCacheHeadAttention: B=32, E=4096 -> D=128, MAX_TOKENS=2048.
// Prefix-softmax: out[b,s,:] = sum_{t<=s} e_t*v[b,t,:] / sum_{t<=s} e_t.
// R3: float4 everywhere on the V/output paths; scan uses all 512 threads
// (8-token sub-chunks, V cached in registers across both passes); prefix
// base loops parallelized (16-way tree / warp reduce). Targets R2's
// issue-bound signature (all pipes ~20%, issue 28.7%).

#define BB 32
#define DD 128
#define D4 32            // DD/4
#define EE 4096
#define MAXT 2048
#define CHUNK 128
#define SUB 32
#define MAXSUB 64        // MAXT/SUB

__device__ float g_qkv[3][BB][DD];
__device__ float g_e[BB][MAXT];
__device__ float g_cnum[BB][MAXSUB][DD];   // 32-token numerator partials
__device__ float g_cden[BB][MAXSUB];

__device__ __forceinline__ float4 f4add(float4 a, float4 b) {
    return make_float4(a.x+b.x, a.y+b.y, a.z+b.z, a.w+b.w);
}
__device__ __forceinline__ float4 f4fma(float s, float4 v, float4 a) {
    return make_float4(fmaf(s,v.x,a.x), fmaf(s,v.y,a.y),
                       fmaf(s,v.z,a.z), fmaf(s,v.w,a.w));
}
__device__ __forceinline__ float4 f4scale(float4 v, float s) {
    return make_float4(v.x*s, v.y*s, v.z*s, v.w*s);
}

// ---------------------------------------------------------------- K0: zero
__global__ void zero_qkv_kernel() {
    int i = blockIdx.x * 256 + threadIdx.x;
    if (i < 3 * BB * DD) ((float*)g_qkv)[i] = 0.0f;
}

// ------------------------------------------------- K1: QKV split-K GEMM
#define ECH 128
__global__ __launch_bounds__(256) void qkv_kernel(
    const float* __restrict__ x, const float* __restrict__ Wq,
    const float* __restrict__ Wk, const float* __restrict__ Wv) {
    __shared__ float xs[32][ECH + 4];
    __shared__ float ws[32][ECH + 4];
    int m  = blockIdx.x >> 2;
    int dt = blockIdx.x & 3;
    const float* W = (m == 0) ? Wq : ((m == 1) ? Wk : Wv);
    int e0  = blockIdx.y * ECH;
    int tid = threadIdx.x;

    for (int i = tid; i < 32 * (ECH / 4); i += 256) {
        int r = i >> 5;
        int j = (i & 31) << 2;
        *(float4*)&xs[r][j] = *(const float4*)(x + (size_t)r * EE + e0 + j);
        *(float4*)&ws[r][j] = *(const float4*)(W + (size_t)(dt * 32 + r) * EE + e0 + j);
    }
    __syncthreads();

    int ti = tid & 15, tj = tid >> 4;
    float a00 = 0.f, a01 = 0.f, a10 = 0.f, a11 = 0.f;
    #pragma unroll
    for (int e = 0; e < ECH; e += 4) {
        float4 xa = *(float4*)&xs[ti][e];
        float4 xb = *(float4*)&xs[ti + 16][e];
        float4 wa = *(float4*)&ws[tj][e];
        float4 wb = *(float4*)&ws[tj + 16][e];
        a00 += xa.x*wa.x + xa.y*wa.y + xa.z*wa.z + xa.w*wa.w;
        a01 += xa.x*wb.x + xa.y*wb.y + xa.z*wb.z + xa.w*wb.w;
        a10 += xb.x*wa.x + xb.y*wa.y + xb.z*wa.z + xb.w*wa.w;
        a11 += xb.x*wb.x + xb.y*wb.y + xb.z*wb.z + xb.w*wb.w;
    }
    atomicAdd(&g_qkv[m][ti][dt * 32 + tj],           a00);
    atomicAdd(&g_qkv[m][ti][dt * 32 + tj + 16],      a01);
    atomicAdd(&g_qkv[m][ti + 16][dt * 32 + tj],      a10);
    atomicAdd(&g_qkv[m][ti + 16][dt * 32 + tj + 16], a11);
}

// ------------- K2: scores -> exp + 32-token sub-chunk num/den partials
// grid(nchunks, B), 512 threads. Phase 2 vectorized: thread = (sc, tq, d4),
// 8 LDG.128 each, quarter-combine via smem.
__global__ __launch_bounds__(512) void score_chunk_kernel(
    const float* __restrict__ kv, const int* __restrict__ np, int max_k) {
    int b = blockIdx.y, c = blockIdx.x, tid = threadIdx.x;
    __shared__ float qs[DD], kn[DD], es[CHUNK];
    __shared__ float4 vns4[D4];
    __shared__ float4 red[4][4][D4];

    if (tid < DD) {
        qs[tid] = g_qkv[0][b][tid];
        kn[tid] = g_qkv[1][b][tid];
        if ((tid & 3) == 0)
            vns4[tid >> 2] = *(const float4*)&g_qkv[2][b][tid];
    }
    __syncthreads();

    int npos = np[b];
    int t0   = c * CHUNK;

    // phase 1: scores. token = tid>>2, quarter-dot per lane.
    {
        int tok = tid >> 2, qq = tid & 3;
        int t   = t0 + tok;
        const float* krow = (t == npos) ? kn
                          : kv + ((size_t)b * MAXT + t) * DD;
        float s = 0.0f;
        int d0 = qq * 32;
        #pragma unroll
        for (int d = 0; d < 32; d += 4) {
            float4 kk = *(const float4*)(krow + d0 + d);
            s += qs[d0+d]*kk.x + qs[d0+d+1]*kk.y + qs[d0+d+2]*kk.z + qs[d0+d+3]*kk.w;
        }
        s += __shfl_xor_sync(0xffffffffu, s, 1);
        s += __shfl_xor_sync(0xffffffffu, s, 2);
        float e = (t < max_k) ? expf(s * 0.08838834764831845f) : 0.0f;
        if (qq == 0) {
            es[tok]   = e;
            g_e[b][t] = e;
        }
    }
    __syncthreads();

    // sub-chunk denominators (32-token): warps 0..3
    if (tid < 128) {
        float de = es[tid];
        #pragma unroll
        for (int o = 16; o; o >>= 1) de += __shfl_xor_sync(0xffffffffu, de, o);
        if ((tid & 31) == 0) g_cden[b][c * 4 + (tid >> 5)] = de;
    }

    // phase 2: numerator partials, vectorized.
    int sc = tid >> 7;            // 0..3   32-token sub-chunk
    int tq = (tid >> 5) & 3;      // 0..3   8-token quarter
    int d4 = tid & 31;            // 0..31  float4 column
    int tb = t0 + sc * SUB + tq * 8;
    const float4* vbase = (const float4*)(kv + (size_t)BB * MAXT * DD
                                          + ((size_t)b * MAXT + tb) * DD) + d4;
    float4 acc = make_float4(0.f, 0.f, 0.f, 0.f);
    #pragma unroll
    for (int u = 0; u < 8; u++) {
        float4 vv = vbase[(size_t)u * D4];          // always in-bounds (<MAXT)
        if (tb + u == npos) vv = vns4[d4];
        acc = f4fma(es[sc * SUB + tq * 8 + u], vv, acc);
    }
    red[sc][tq][d4] = acc;
    __syncthreads();
    if (tid < 128) {
        int sc2 = tid >> 5, dd = tid & 31;
        float4 s0 = f4add(f4add(red[sc2][0][dd], red[sc2][1][dd]),
                          f4add(red[sc2][2][dd], red[sc2][3][dd]));
        *((float4*)&g_cnum[b][c * 4 + sc2][0] + dd) = s0;
    }
}

// --------- K3: prefix scan, 8-token granularity, V in registers
// grid(nchunks, B), 512 threads, thread = (sc8 in 0..15, d4 in 0..31).
__global__ __launch_bounds__(512) void scan_kernel(
    const float* __restrict__ kv, const int* __restrict__ np,
    float* __restrict__ out, int max_k) {
    int b = blockIdx.y, c = blockIdx.x, tid = threadIdx.x;
    __shared__ float es[CHUNK], rden[CHUNK];
    __shared__ float4 vns4[D4];
    __shared__ float4 bred[16][D4];     // chunk-base slice reduction
    __shared__ float4 part[16][D4];     // 8-token partials
    __shared__ float warp_sums[4];
    __shared__ float denbase_s;

    int t0 = c * CHUNK;
    if (tid < DD) {
        es[tid] = g_e[b][t0 + tid];
        if ((tid & 3) == 0)
            vns4[tid >> 2] = *(const float4*)&g_qkv[2][b][tid];
    }

    int s  = tid >> 5;       // 0..15
    int d4 = tid & 31;       // 0..31

    // chunk numerator base: rows i < 4c, strided by 16 slices + tree combine
    {
        float4 acc = make_float4(0.f, 0.f, 0.f, 0.f);
        int nrow = 4 * c;
        for (int i = s; i < nrow; i += 16)
            acc = f4add(acc, *((const float4*)&g_cnum[b][i][0] + d4));
        bred[s][d4] = acc;
    }
    // denominator base: warp 0 only
    if (tid < 32) {
        float db = 0.0f;
        int nrow = 4 * c;
        for (int i = tid; i < nrow; i += 32) db += g_cden[b][i];
        #pragma unroll
        for (int o = 16; o; o >>= 1) db += __shfl_xor_sync(0xffffffffu, db, o);
        if (tid == 0) denbase_s = db;
    }
    __syncthreads();
    #pragma unroll
    for (int off = 8; off; off >>= 1) {
        if (s < off) bred[s][d4] = f4add(bred[s][d4], bred[s + off][d4]);
        __syncthreads();
    }

    // denominator prefixes across the 128 tokens
    if (tid < 128) {
        float v = es[tid];
        int lane = tid & 31;
        #pragma unroll
        for (int o = 1; o < 32; o <<= 1) {
            float n = __shfl_up_sync(0xffffffffu, v, o);
            if (lane >= o) v += n;
        }
        if (lane == 31) warp_sums[tid >> 5] = v;
        __syncthreads();
        int w = tid >> 5;
        float wb = denbase_s;
        for (int i = 0; i < w; i++) wb += warp_sums[i];
        rden[tid] = 1.0f / (wb + v);
    } else {
        __syncthreads();
    }

    // V into registers + 8-token partial
    int npos = np[b];
    int tb   = t0 + s * 8;
    const float4* vbase = (const float4*)(kv + (size_t)BB * MAXT * DD
                                          + ((size_t)b * MAXT + tb) * DD) + d4;
    float4 vv[8];
    float4 psum = make_float4(0.f, 0.f, 0.f, 0.f);
    #pragma unroll
    for (int u = 0; u < 8; u++) {
        float4 x = vbase[(size_t)u * D4];
        if (tb + u == npos) x = vns4[d4];
        vv[u] = x;
        psum = f4fma(es[s * 8 + u], x, psum);
    }
    part[s][d4] = psum;
    __syncthreads();

    // base = chunk base + earlier 8-token partials in this chunk
    float4 acc = bred[0][d4];
    for (int j = 0; j < s; j++) acc = f4add(acc, part[j][d4]);

    // scan + write
    float4* obase = (float4*)(out + ((size_t)b * max_k + tb) * DD) + d4;
    #pragma unroll
    for (int u = 0; u < 8; u++) {
        acc = f4fma(es[s * 8 + u], vv[u], acc);
        if (tb + u < max_k)
            obase[(size_t)u * D4] = f4scale(acc, rden[s * 8 + u]);
    }
}

// ----------------------------------------------------------------- launch
extern "C" void kernel_launch(void* const* d_in, const int* in_sizes, int n_in,
                              void* d_out, int out_size) {
    const float* x   = (const float*)d_in[0];
    const float* Wq  = (const float*)d_in[1];
    const float* Wk  = (const float*)d_in[2];
    const float* Wv  = (const float*)d_in[3];
    const float* kvc = (const float*)d_in[4];
    const int*   np  = (const int*)d_in[5];
    float* out = (float*)d_out;

    int max_k   = out_size / (BB * DD);
    int nchunks = (max_k + CHUNK - 1) / CHUNK;

    zero_qkv_kernel<<<48, 256>>>();
    qkv_kernel<<<dim3(12, 32), 256>>>(x, Wq, Wk, Wv);
    score_chunk_kernel<<<dim3(nchunks, BB), 512>>>(kvc, np, max_k);
    scan_kernel<<<dim3(nchunks, BB), 512>>>(kvc, np, out, max_k);
}